// round 10
// baseline (speedup 1.0000x reference)
#include <cuda_runtime.h>
#include <cuda_fp16.h>
#include <cstdint>

// TopKRouter via mma.sync f16 (hi/lo split, 3-pass): logits = x@W + b ; softmax E=64 ; top-2
// x: (16384, 2048) fp32, W: (2048, 64) fp32, b: (64,)
// out f32: [0..2M) = topk_idx as float (M,2) ; [2M..4M) = topk_vals (M,2)
// R8: 256 threads, 8 warps = 2 token-halves x 4 K-quarters; same smem traffic, 2x occupancy.

#define DK 2048
#define NE 64
#define KS 64
#define MTILE 32
#define NSLAB (DK / KS)         // 32
#define NTHREADS 256
#define SCALE_LO 2048.0f
#define INV_LO   4.8828125e-4f  // 2^-11

#define BUF_BYTES 24576         // Ah(4K) Al(4K) Bh(8K) Bl(8K)
#define OFF_AH 0
#define OFF_AL 4096
#define OFF_BH 8192
#define OFF_BL 16384
#define OFF_BIAS (2 * BUF_BYTES)
#define SMEM_TOTAL (OFF_BIAS + 512)

#define SWZ(a) ((a) ^ (((a) >> 3) & 0x70))

__device__ uint16_t g_Wh[DK * NE];
__device__ uint16_t g_Wl[DK * NE];

__device__ __forceinline__ uint32_t su32(const void* p) {
    uint32_t a;
    asm("{ .reg .u64 t; cvta.to.shared.u64 t, %1; cvt.u32.u64 %0, t; }" : "=r"(a) : "l"(p));
    return a;
}
__device__ __forceinline__ void cp_async16(uint32_t saddr, const void* g) {
    asm volatile("cp.async.cg.shared.global [%0], [%1], 16;" :: "r"(saddr), "l"(g));
}
#define CP_COMMIT() asm volatile("cp.async.commit_group;" ::: "memory")
#define CP_WAIT0()  asm volatile("cp.async.wait_group 0;" ::: "memory")

__device__ __forceinline__ void split_h(float v, uint16_t& h, uint16_t& l) {
    __half hh = __float2half_rn(v);
    float r = (v - __half2float(hh)) * SCALE_LO;
    __half ll = __float2half_rn(r);
    h = __half_as_ushort(hh);
    l = __half_as_ushort(ll);
}

#define LDSM_X4(r0, r1, r2, r3, a)                                             \
    asm volatile("ldmatrix.sync.aligned.m8n8.x4.shared.b16 {%0,%1,%2,%3}, [%4];" \
                 : "=r"(r0), "=r"(r1), "=r"(r2), "=r"(r3) : "r"(a))
#define LDSM_X4T(r0, r1, r2, r3, a)                                            \
    asm volatile("ldmatrix.sync.aligned.m8n8.x4.trans.shared.b16 {%0,%1,%2,%3}, [%4];" \
                 : "=r"(r0), "=r"(r1), "=r"(r2), "=r"(r3) : "r"(a))

#define MMA16816(d, a0, a1, a2, a3, b0, b1)                                    \
    asm volatile("mma.sync.aligned.m16n8k16.row.col.f32.f16.f16.f32 "          \
                 "{%0,%1,%2,%3}, {%4,%5,%6,%7}, {%8,%9}, {%0,%1,%2,%3};"       \
                 : "+f"((d)[0]), "+f"((d)[1]), "+f"((d)[2]), "+f"((d)[3])      \
                 : "r"(a0), "r"(a1), "r"(a2), "r"(a3), "r"(b0), "r"(b1))

__global__ void wconv_kernel(const float* __restrict__ W) {
    int i = (blockIdx.x * blockDim.x + threadIdx.x) * 4;
    float4 v = *(const float4*)(W + i);
    uint16_t h[4], l[4];
    split_h(v.x, h[0], l[0]); split_h(v.y, h[1], l[1]);
    split_h(v.z, h[2], l[2]); split_h(v.w, h[3], l[3]);
    *(uint2*)(g_Wh + i) = make_uint2((uint32_t)h[0] | ((uint32_t)h[1] << 16),
                                     (uint32_t)h[2] | ((uint32_t)h[3] << 16));
    *(uint2*)(g_Wl + i) = make_uint2((uint32_t)l[0] | ((uint32_t)l[1] << 16),
                                     (uint32_t)l[2] | ((uint32_t)l[3] << 16));
}

// A slab: 32 tokens x 64 k fp32 = 512 float4 -> 2 per thread (256 threads)
__device__ __forceinline__ void issue_A(const float* __restrict__ x, float4* xa,
                                        int m0, int c, int tid) {
#pragma unroll
    for (int r = 0; r < 2; r++) {
        int lin = r * NTHREADS + tid;
        int m = lin >> 4, kq = lin & 15;
        xa[r] = *(const float4*)(x + (size_t)(m0 + m) * DK + c * KS + kq * 4);
    }
}
__device__ __forceinline__ void store_A(char* smem, int buf, const float4* xa, int tid) {
    char* base = smem + buf * BUF_BYTES;
#pragma unroll
    for (int r = 0; r < 2; r++) {
        int lin = r * NTHREADS + tid;
        int m = lin >> 4, kq = lin & 15;
        uint16_t h[4], l[4];
        split_h(xa[r].x, h[0], l[0]); split_h(xa[r].y, h[1], l[1]);
        split_h(xa[r].z, h[2], l[2]); split_h(xa[r].w, h[3], l[3]);
        uint32_t off = SWZ((uint32_t)(m * 128 + kq * 8));
        *(uint2*)(base + OFF_AH + off) =
            make_uint2((uint32_t)h[0] | ((uint32_t)h[1] << 16),
                       (uint32_t)h[2] | ((uint32_t)h[3] << 16));
        *(uint2*)(base + OFF_AL + off) =
            make_uint2((uint32_t)l[0] | ((uint32_t)l[1] << 16),
                       (uint32_t)l[2] | ((uint32_t)l[3] << 16));
    }
}
__device__ __forceinline__ void issue_B(uint32_t sb, int buf, int c, int tid) {
    uint32_t dst = sb + buf * BUF_BYTES;
#pragma unroll
    for (int r = 0; r < 2; r++) {
        int lin = r * NTHREADS + tid;
        int k = lin >> 3, q = lin & 7;
        uint32_t off = SWZ((uint32_t)(k * 128 + q * 16));
        size_t ge = (size_t)(c * KS + k) * NE + q * 8;
        cp_async16(dst + OFF_BH + off, (const char*)g_Wh + ge * 2);
        cp_async16(dst + OFF_BL + off, (const char*)g_Wl + ge * 2);
    }
    CP_COMMIT();
}

__global__ __launch_bounds__(NTHREADS)
void router_kernel(const float* __restrict__ x,
                   const float* __restrict__ bias,
                   float* __restrict__ out,
                   int M)
{
    extern __shared__ char smem[];
    const uint32_t sb = su32(smem);
    const int tid = threadIdx.x;
    const int wid = tid >> 5;
    const int lid = tid & 31;
    const int m0  = blockIdx.x * MTILE;
    const int mhalf = wid & 1;      // which 16-token half
    const int kq4   = wid >> 1;     // which 16-k quarter of each 64-k slab
    float* bias_sm = (float*)(smem + OFF_BIAS);

    if (tid < NE) bias_sm[tid] = bias[tid];

    float acch[8][4], accl[8][4];
#pragma unroll
    for (int j = 0; j < 8; j++)
#pragma unroll
        for (int i = 0; i < 4; i++) { acch[j][i] = 0.f; accl[j][i] = 0.f; }

    float4 xa[2];
    issue_B(sb, 0, 0, tid);
    issue_A(x, xa, m0, 0, tid);
    store_A(smem, 0, xa, tid);
    CP_WAIT0();
    __syncthreads();

    const int lr = lid & 7;
    const int lg = lid >> 3;

#pragma unroll 1
    for (int c = 0; c < NSLAB; ++c) {
        const int p = c & 1, q = p ^ 1;
        const bool more = (c + 1 < NSLAB);
        if (more) {
            issue_B(sb, q, c + 1, tid);
            issue_A(x, xa, m0, c + 1, tid);
        }

        const uint32_t bufb = sb + p * BUF_BYTES;
        {
            uint32_t a_off = SWZ((uint32_t)((mhalf * 16 + (lg & 1) * 8 + lr) * 128
                                            + kq4 * 32 + (lg >> 1) * 16));
            uint32_t ah0, ah1, ah2, ah3, al0, al1, al2, al3;
            LDSM_X4(ah0, ah1, ah2, ah3, bufb + OFF_AH + a_off);
            LDSM_X4(al0, al1, al2, al3, bufb + OFF_AL + a_off);

            uint32_t bh[16], bl[16];
#pragma unroll
            for (int j2 = 0; j2 < 4; j2++) {
                uint32_t b_off = SWZ((uint32_t)((kq4 * 16 + (lg & 1) * 8 + lr) * 128
                                                + (j2 * 16 + (lg >> 1) * 8) * 2));
                LDSM_X4T(bh[j2 * 4 + 0], bh[j2 * 4 + 1], bh[j2 * 4 + 2], bh[j2 * 4 + 3],
                         bufb + OFF_BH + b_off);
                LDSM_X4T(bl[j2 * 4 + 0], bl[j2 * 4 + 1], bl[j2 * 4 + 2], bl[j2 * 4 + 3],
                         bufb + OFF_BL + b_off);
            }
#pragma unroll
            for (int j = 0; j < 8; j++) {
                uint32_t b0h = bh[(j >> 1) * 4 + (j & 1) * 2];
                uint32_t b1h = bh[(j >> 1) * 4 + (j & 1) * 2 + 1];
                uint32_t b0l = bl[(j >> 1) * 4 + (j & 1) * 2];
                uint32_t b1l = bl[(j >> 1) * 4 + (j & 1) * 2 + 1];
                MMA16816(acch[j], ah0, ah1, ah2, ah3, b0h, b1h);
                MMA16816(accl[j], ah0, ah1, ah2, ah3, b0l, b1l);
                MMA16816(accl[j], al0, al1, al2, al3, b0h, b1h);
            }
        }

        if (more) { store_A(smem, q, xa, tid); CP_WAIT0(); }
        __syncthreads();
    }

    // ---- epilogue: combine hi/lo, 4-way K reduction via smem, softmax + top-2 ----
    const int qr = lid >> 2;
    const int qc = lid & 3;
    float L[2][16];
#pragma unroll
    for (int j = 0; j < 8; j++) {
        L[0][j * 2 + 0] = acch[j][0] + accl[j][0] * INV_LO;
        L[0][j * 2 + 1] = acch[j][1] + accl[j][1] * INV_LO;
        L[1][j * 2 + 0] = acch[j][2] + accl[j][2] * INV_LO;
        L[1][j * 2 + 1] = acch[j][3] + accl[j][3] * INV_LO;
    }

    float* ex = (float*)smem;          // [3 quarters][32 tokens][66]
    if (kq4 != 0) {
        float* exq = ex + (size_t)(kq4 - 1) * 32 * 66;
#pragma unroll
        for (int t = 0; t < 2; t++) {
            int token = mhalf * 16 + t * 8 + qr;
#pragma unroll
            for (int j = 0; j < 8; j++) {
                int e = j * 8 + qc * 2;
                *(float2*)&exq[token * 66 + e] = make_float2(L[t][j * 2], L[t][j * 2 + 1]);
            }
        }
    }
    __syncthreads();

    if (kq4 == 0) {
#pragma unroll
        for (int t = 0; t < 2; t++) {
            int token = mhalf * 16 + t * 8 + qr;
            float Lf[16];
#pragma unroll
            for (int j = 0; j < 8; j++) {
                int e = j * 8 + qc * 2;
                float2 o1 = *(const float2*)&ex[(size_t)0 * 32 * 66 + token * 66 + e];
                float2 o2 = *(const float2*)&ex[(size_t)1 * 32 * 66 + token * 66 + e];
                float2 o3 = *(const float2*)&ex[(size_t)2 * 32 * 66 + token * 66 + e];
                Lf[j * 2 + 0] = L[t][j * 2 + 0] + o1.x + o2.x + o3.x + bias_sm[e];
                Lf[j * 2 + 1] = L[t][j * 2 + 1] + o1.y + o2.y + o3.y + bias_sm[e + 1];
            }
            float v1 = -3.402823466e38f, v2 = -3.402823466e38f;
            int i1 = 0, i2 = 0;
#pragma unroll
            for (int u = 0; u < 16; u++) {
                int e = (u >> 1) * 8 + qc * 2 + (u & 1);
                float v = Lf[u];
                if (v > v1)      { v2 = v1; i2 = i1; v1 = v; i1 = e; }
                else if (v > v2) { v2 = v;  i2 = e; }
            }
#pragma unroll
            for (int d = 1; d <= 2; d <<= 1) {
                float w1 = __shfl_xor_sync(0xffffffffu, v1, d);
                int   j1 = __shfl_xor_sync(0xffffffffu, i1, d);
                float w2 = __shfl_xor_sync(0xffffffffu, v2, d);
                int   j2 = __shfl_xor_sync(0xffffffffu, i2, d);
                float c2v; int c2i;
                if (w1 > v1) { c2v = v1; c2i = i1; v1 = w1; i1 = j1; }
                else         { c2v = w1; c2i = j1; }
                if (c2v > v2) { v2 = c2v; i2 = c2i; }
                if (w2 > v2)  { v2 = w2;  i2 = j2; }
            }
            float s = 0.f;
#pragma unroll
            for (int u = 0; u < 16; u++) s += __expf(Lf[u] - v1);
#pragma unroll
            for (int d = 1; d <= 2; d <<= 1) s += __shfl_xor_sync(0xffffffffu, s, d);

            if (qc == 0) {
                int g = m0 + token;
                out[2 * g + 0] = (float)i1;
                out[2 * g + 1] = (float)i2;
                size_t voff = (size_t)2 * M;
                out[voff + 2 * g + 0] = 1.0f / s;
                out[voff + 2 * g + 1] = __expf(v2 - v1) / s;
            }
        }
    }
}

extern "C" void kernel_launch(void* const* d_in, const int* in_sizes, int n_in,
                              void* d_out, int out_size) {
    const float* x  = (const float*)d_in[0];
    const float* W  = (const float*)d_in[1];
    const float* b  = (const float*)d_in[2];
    float* out = (float*)d_out;

    int M = in_sizes[0] / DK;   // 16384
    wconv_kernel<<<(DK * NE / 4 + 255) / 256, 256>>>(W);
    cudaFuncSetAttribute(router_kernel,
                         cudaFuncAttributeMaxDynamicSharedMemorySize, SMEM_TOTAL);
    router_kernel<<<M / MTILE, NTHREADS, SMEM_TOTAL>>>(x, b, out, M);
}

// round 11
// speedup vs baseline: 1.3135x; 1.3135x over previous
#include <cuda_runtime.h>
#include <cuda_fp16.h>
#include <cstdint>

// TopKRouter via mma.sync f16 (hi/lo split, 3-pass): logits = x@W + b ; softmax E=64 ; top-2
// x: (16384, 2048) fp32, W: (2048, 64) fp32, b: (64,)
// out f32: [0..2M) = topk_idx as float (M,2) ; [2M..4M) = topk_vals (M,2)
// R11: R7 base (MTILE=32, 4 warps, K-split halves) + MMA pass-splitting for ILP
//      (accumulator reuse distance 1 -> 8) + launch_bounds regs cap.

#define DK 2048
#define NE 64
#define KS 64
#define MTILE 32
#define NSLAB (DK / KS)         // 32
#define NTHREADS 128
#define SCALE_LO 2048.0f
#define INV_LO   4.8828125e-4f  // 2^-11

#define BUF_BYTES 24576
#define OFF_AH 0
#define OFF_AL 4096
#define OFF_BH 8192
#define OFF_BL 16384
#define OFF_BIAS (2 * BUF_BYTES)
#define SMEM_TOTAL (OFF_BIAS + 512)

#define SWZ(a) ((a) ^ (((a) >> 3) & 0x70))

__device__ uint16_t g_Wh[DK * NE];
__device__ uint16_t g_Wl[DK * NE];

__device__ __forceinline__ uint32_t su32(const void* p) {
    uint32_t a;
    asm("{ .reg .u64 t; cvta.to.shared.u64 t, %1; cvt.u32.u64 %0, t; }" : "=r"(a) : "l"(p));
    return a;
}
__device__ __forceinline__ void cp_async16(uint32_t saddr, const void* g) {
    asm volatile("cp.async.cg.shared.global [%0], [%1], 16;" :: "r"(saddr), "l"(g));
}
#define CP_COMMIT() asm volatile("cp.async.commit_group;" ::: "memory")
#define CP_WAIT0()  asm volatile("cp.async.wait_group 0;" ::: "memory")

__device__ __forceinline__ void split_h(float v, uint16_t& h, uint16_t& l) {
    __half hh = __float2half_rn(v);
    float r = (v - __half2float(hh)) * SCALE_LO;
    __half ll = __float2half_rn(r);
    h = __half_as_ushort(hh);
    l = __half_as_ushort(ll);
}

#define LDSM_X4(r0, r1, r2, r3, a)                                             \
    asm volatile("ldmatrix.sync.aligned.m8n8.x4.shared.b16 {%0,%1,%2,%3}, [%4];" \
                 : "=r"(r0), "=r"(r1), "=r"(r2), "=r"(r3) : "r"(a))
#define LDSM_X4T(r0, r1, r2, r3, a)                                            \
    asm volatile("ldmatrix.sync.aligned.m8n8.x4.trans.shared.b16 {%0,%1,%2,%3}, [%4];" \
                 : "=r"(r0), "=r"(r1), "=r"(r2), "=r"(r3) : "r"(a))

#define MMA16816(d, a0, a1, a2, a3, b0, b1)                                    \
    asm volatile("mma.sync.aligned.m16n8k16.row.col.f32.f16.f16.f32 "          \
                 "{%0,%1,%2,%3}, {%4,%5,%6,%7}, {%8,%9}, {%0,%1,%2,%3};"       \
                 : "+f"((d)[0]), "+f"((d)[1]), "+f"((d)[2]), "+f"((d)[3])      \
                 : "r"(a0), "r"(a1), "r"(a2), "r"(a3), "r"(b0), "r"(b1))

__global__ void wconv_kernel(const float* __restrict__ W) {
    int i = (blockIdx.x * blockDim.x + threadIdx.x) * 4;
    float4 v = *(const float4*)(W + i);
    uint16_t h[4], l[4];
    split_h(v.x, h[0], l[0]); split_h(v.y, h[1], l[1]);
    split_h(v.z, h[2], l[2]); split_h(v.w, h[3], l[3]);
    *(uint2*)(g_Wh + i) = make_uint2((uint32_t)h[0] | ((uint32_t)h[1] << 16),
                                     (uint32_t)h[2] | ((uint32_t)h[3] << 16));
    *(uint2*)(g_Wl + i) = make_uint2((uint32_t)l[0] | ((uint32_t)l[1] << 16),
                                     (uint32_t)l[2] | ((uint32_t)l[3] << 16));
}

__device__ __forceinline__ void issue_A(const float* __restrict__ x, float4* xa,
                                        int m0, int c, int tid) {
#pragma unroll
    for (int r = 0; r < 4; r++) {
        int lin = r * NTHREADS + tid;
        int m = lin >> 4, kq = lin & 15;
        xa[r] = *(const float4*)(x + (size_t)(m0 + m) * DK + c * KS + kq * 4);
    }
}
__device__ __forceinline__ void store_A(char* smem, int buf, const float4* xa, int tid) {
    char* base = smem + buf * BUF_BYTES;
#pragma unroll
    for (int r = 0; r < 4; r++) {
        int lin = r * NTHREADS + tid;
        int m = lin >> 4, kq = lin & 15;
        uint16_t h[4], l[4];
        split_h(xa[r].x, h[0], l[0]); split_h(xa[r].y, h[1], l[1]);
        split_h(xa[r].z, h[2], l[2]); split_h(xa[r].w, h[3], l[3]);
        uint32_t off = SWZ((uint32_t)(m * 128 + kq * 8));
        *(uint2*)(base + OFF_AH + off) =
            make_uint2((uint32_t)h[0] | ((uint32_t)h[1] << 16),
                       (uint32_t)h[2] | ((uint32_t)h[3] << 16));
        *(uint2*)(base + OFF_AL + off) =
            make_uint2((uint32_t)l[0] | ((uint32_t)l[1] << 16),
                       (uint32_t)l[2] | ((uint32_t)l[3] << 16));
    }
}
__device__ __forceinline__ void issue_B(uint32_t sb, int buf, int c, int tid) {
    uint32_t dst = sb + buf * BUF_BYTES;
#pragma unroll
    for (int r = 0; r < 4; r++) {
        int lin = r * NTHREADS + tid;
        int k = lin >> 3, q = lin & 7;
        uint32_t off = SWZ((uint32_t)(k * 128 + q * 16));
        size_t ge = (size_t)(c * KS + k) * NE + q * 8;
        cp_async16(dst + OFF_BH + off, (const char*)g_Wh + ge * 2);
        cp_async16(dst + OFF_BL + off, (const char*)g_Wl + ge * 2);
    }
    CP_COMMIT();
}

__global__ __launch_bounds__(NTHREADS, 4)
void router_kernel(const float* __restrict__ x,
                   const float* __restrict__ bias,
                   float* __restrict__ out,
                   int M)
{
    extern __shared__ char smem[];
    const uint32_t sb = su32(smem);
    const int tid = threadIdx.x;
    const int wid = tid >> 5;
    const int lid = tid & 31;
    const int m0  = blockIdx.x * MTILE;
    const int mhalf = wid & 1;      // which 16-token half
    const int khalf = wid >> 1;     // which 32-k half of each slab
    float* bias_sm = (float*)(smem + OFF_BIAS);

    if (tid < NE) bias_sm[tid] = bias[tid];

    float acch[8][4], accl[8][4];
#pragma unroll
    for (int j = 0; j < 8; j++)
#pragma unroll
        for (int i = 0; i < 4; i++) { acch[j][i] = 0.f; accl[j][i] = 0.f; }

    float4 xa[4];
    issue_B(sb, 0, 0, tid);
    issue_A(x, xa, m0, 0, tid);
    store_A(smem, 0, xa, tid);
    CP_WAIT0();
    __syncthreads();

    const int lr = lid & 7;
    const int lg = lid >> 3;

#pragma unroll 1
    for (int c = 0; c < NSLAB; ++c) {
        const int p = c & 1, q = p ^ 1;
        const bool more = (c + 1 < NSLAB);
        if (more) {
            issue_B(sb, q, c + 1, tid);
            issue_A(x, xa, m0, c + 1, tid);
        }

        const uint32_t bufb = sb + p * BUF_BYTES;
#pragma unroll
        for (int s = 0; s < 2; s++) {
            uint32_t a_off = SWZ((uint32_t)((mhalf * 16 + (lg & 1) * 8 + lr) * 128
                                            + khalf * 64 + s * 32 + (lg >> 1) * 16));
            uint32_t ah0, ah1, ah2, ah3, al0, al1, al2, al3;
            LDSM_X4(ah0, ah1, ah2, ah3, bufb + OFF_AH + a_off);
            LDSM_X4(al0, al1, al2, al3, bufb + OFF_AL + a_off);

            uint32_t bh[16], bl[16];
#pragma unroll
            for (int j2 = 0; j2 < 4; j2++) {
                uint32_t b_off = SWZ((uint32_t)((khalf * 32 + s * 16 + (lg & 1) * 8 + lr) * 128
                                                + (j2 * 16 + (lg >> 1) * 8) * 2));
                LDSM_X4T(bh[j2 * 4 + 0], bh[j2 * 4 + 1], bh[j2 * 4 + 2], bh[j2 * 4 + 3],
                         bufb + OFF_BH + b_off);
                LDSM_X4T(bl[j2 * 4 + 0], bl[j2 * 4 + 1], bl[j2 * 4 + 2], bl[j2 * 4 + 3],
                         bufb + OFF_BL + b_off);
            }
            // pass 1: acch += ah * bh   (independent across j)
#pragma unroll
            for (int j = 0; j < 8; j++)
                MMA16816(acch[j], ah0, ah1, ah2, ah3,
                         bh[(j >> 1) * 4 + (j & 1) * 2], bh[(j >> 1) * 4 + (j & 1) * 2 + 1]);
            // pass 2: accl += ah * bl   (accl[j] reuse distance = 8 vs pass 3)
#pragma unroll
            for (int j = 0; j < 8; j++)
                MMA16816(accl[j], ah0, ah1, ah2, ah3,
                         bl[(j >> 1) * 4 + (j & 1) * 2], bl[(j >> 1) * 4 + (j & 1) * 2 + 1]);
            // pass 3: accl += al * bh
#pragma unroll
            for (int j = 0; j < 8; j++)
                MMA16816(accl[j], al0, al1, al2, al3,
                         bh[(j >> 1) * 4 + (j & 1) * 2], bh[(j >> 1) * 4 + (j & 1) * 2 + 1]);
        }

        if (more) { store_A(smem, q, xa, tid); CP_WAIT0(); }
        __syncthreads();
    }

    // ---- epilogue: combine hi/lo, exchange K-halves via smem, softmax + top-2 ----
    const int qr = lid >> 2;
    const int qc = lid & 3;
    float L[2][16];
#pragma unroll
    for (int j = 0; j < 8; j++) {
        L[0][j * 2 + 0] = acch[j][0] + accl[j][0] * INV_LO;
        L[0][j * 2 + 1] = acch[j][1] + accl[j][1] * INV_LO;
        L[1][j * 2 + 0] = acch[j][2] + accl[j][2] * INV_LO;
        L[1][j * 2 + 1] = acch[j][3] + accl[j][3] * INV_LO;
    }

    float* ex = (float*)smem;          // [32 tokens][66] K-half exchange
    if (khalf == 1) {
#pragma unroll
        for (int t = 0; t < 2; t++) {
            int token = mhalf * 16 + t * 8 + qr;
#pragma unroll
            for (int j = 0; j < 8; j++) {
                int e = j * 8 + qc * 2;
                *(float2*)&ex[token * 66 + e] = make_float2(L[t][j * 2], L[t][j * 2 + 1]);
            }
        }
    }
    __syncthreads();

    if (khalf == 0) {
#pragma unroll
        for (int t = 0; t < 2; t++) {
            int token = mhalf * 16 + t * 8 + qr;
            float Lf[16];
#pragma unroll
            for (int j = 0; j < 8; j++) {
                int e = j * 8 + qc * 2;
                float2 o = *(const float2*)&ex[token * 66 + e];
                Lf[j * 2 + 0] = L[t][j * 2 + 0] + o.x + bias_sm[e];
                Lf[j * 2 + 1] = L[t][j * 2 + 1] + o.y + bias_sm[e + 1];
            }
            float v1 = -3.402823466e38f, v2 = -3.402823466e38f;
            int i1 = 0, i2 = 0;
#pragma unroll
            for (int u = 0; u < 16; u++) {
                int e = (u >> 1) * 8 + qc * 2 + (u & 1);
                float v = Lf[u];
                if (v > v1)      { v2 = v1; i2 = i1; v1 = v; i1 = e; }
                else if (v > v2) { v2 = v;  i2 = e; }
            }
#pragma unroll
            for (int d = 1; d <= 2; d <<= 1) {
                float w1 = __shfl_xor_sync(0xffffffffu, v1, d);
                int   j1 = __shfl_xor_sync(0xffffffffu, i1, d);
                float w2 = __shfl_xor_sync(0xffffffffu, v2, d);
                int   j2 = __shfl_xor_sync(0xffffffffu, i2, d);
                float c2v; int c2i;
                if (w1 > v1) { c2v = v1; c2i = i1; v1 = w1; i1 = j1; }
                else         { c2v = w1; c2i = j1; }
                if (c2v > v2) { v2 = c2v; i2 = c2i; }
                if (w2 > v2)  { v2 = w2;  i2 = j2; }
            }
            float s = 0.f;
#pragma unroll
            for (int u = 0; u < 16; u++) s += __expf(Lf[u] - v1);
#pragma unroll
            for (int d = 1; d <= 2; d <<= 1) s += __shfl_xor_sync(0xffffffffu, s, d);

            if (qc == 0) {
                int g = m0 + token;
                out[2 * g + 0] = (float)i1;
                out[2 * g + 1] = (float)i2;
                size_t voff = (size_t)2 * M;
                out[voff + 2 * g + 0] = 1.0f / s;
                out[voff + 2 * g + 1] = __expf(v2 - v1) / s;
            }
        }
    }
}

extern "C" void kernel_launch(void* const* d_in, const int* in_sizes, int n_in,
                              void* d_out, int out_size) {
    const float* x  = (const float*)d_in[0];
    const float* W  = (const float*)d_in[1];
    const float* b  = (const float*)d_in[2];
    float* out = (float*)d_out;

    int M = in_sizes[0] / DK;   // 16384
    wconv_kernel<<<(DK * NE / 4 + 255) / 256, 256>>>(W);
    cudaFuncSetAttribute(router_kernel,
                         cudaFuncAttributeMaxDynamicSharedMemorySize, SMEM_TOTAL);
    router_kernel<<<M / MTILE, NTHREADS, SMEM_TOTAL>>>(x, b, out, M);
}